// round 9
// baseline (speedup 1.0000x reference)
#include <cuda_runtime.h>
#include <cstdint>

// Problem sizes
#define S    4096
#define II   64
#define H    1024
#define NCTA 128
#define UPC  8        // hidden units per CTA (1 per warp, 8 warps)
#define NW   (NCTA * UPC)   // 1024 warp-publishes per step

// ---------------------------------------------------------------------------
// Device-global scratch (allocation-free rule: __device__ arrays only)
//
// g_h:  double-buffered hidden state (plain f32; h_t lives in slot t&1).
// g_cnt: monotonic warp-step counter. Each warp does ONE
//        red.release.gpu.add(+1) right after publishing its h value; a CTA
//        enters step t only after an acquire-load sees cnt >= 1024*t.
//        release->acquire + __syncthreads makes all h stores visible to the
//        whole CTA, so the h sweep can use cheap WEAK loads (no tags).
//        (Tagged-atom scheme from R7/R8 retired: tags were only needed
//        because the sweep polled concurrently-written lines; the gate makes
//        the sweep single-shot on stable data.)
// ---------------------------------------------------------------------------
__device__ float    g_h[2][H];
__device__ unsigned g_cnt;

// ---------------------------------------------------------------------------
// Helpers
// ---------------------------------------------------------------------------
__device__ __forceinline__ unsigned long long pk2(float x, float y) {
    unsigned long long r;
    asm("mov.b64 %0, {%1,%2};" : "=l"(r) : "f"(x), "f"(y));
    return r;
}
__device__ __forceinline__ void upk2(unsigned long long a, float& x, float& y) {
    asm("mov.b64 {%0,%1}, %2;" : "=f"(x), "=f"(y) : "l"(a));
}
#define FMA2(acc, a, b) \
    asm("fma.rn.f32x2 %0, %1, %2, %0;" : "+l"(acc) : "l"(a), "l"(b))

__device__ __forceinline__ float sigf(float x) {
    return 1.0f / (1.0f + __expf(-x));
}
__device__ __forceinline__ float tanhfast(float x) {
    float ax = fabsf(x);
    float e  = __expf(-2.0f * ax);          // in (0,1], overflow-free
    float t  = __fdividef(1.0f - e, 1.0f + e);
    return copysignf(t, x);
}

// ---------------------------------------------------------------------------
// Kernel 0: reset state between graph replays (determinism requirement)
// ---------------------------------------------------------------------------
__global__ void reset_kernel() {
    int i = threadIdx.x;
    if (i < H) { g_h[0][i] = 0.0f; g_h[1][i] = 0.0f; }
    if (i == 0) g_cnt = 0u;
}

// no-op padding kernels: shift ncu's "-s 5 -c 1" capture window onto
// rec_kernel (7 launches per replay, rec at index 5). Zero-cost graph nodes.
__global__ void nop_kernel() {}

// ---------------------------------------------------------------------------
// Kernel 1: persistent fused LSTM recurrence (input GEMM folded in).
// 128 CTAs x 256 threads, 1 CTA/SM (register bound). Warp w of CTA b owns
// hidden unit u = b*8 + w (gate rows u, H+u, 2H+u, 3H+u).
// Lane l holds W_hh column pairs (2l+64k) k=0..15 (64 packed f32x2) plus
// W_ih column pair 2l (4 packed f32x2) in registers for all 4096 steps.
//
// Per-step protocol (TWO __syncthreads, everything else free-running):
//   1. prefetch x_{t+1} (tid<16, 256 B, triple-buffered SMEM)
//   2. GATE: tid 0 spins ld.acquire.gpu on g_cnt until >= 1024*t
//   3. bar A  (acquire ordering extends to whole CTA)
//   4. SWEEP: one WEAK __ldcg float4 per thread -> hs[t&1]
//   5. bar B
//   6. matvec (LDS.64 + FMA2, W_hh + W_ih) -> shfl reduce -> activations
//   7. lane 0: weak __stcg publish of h_{t+1}[u], then
//      red.release.gpu.add(g_cnt, 1)  -- release orders the publish (and all
//      prior reads, closing the WAR window) before the count becomes visible.
//      No trailing bar: each warp signals the moment it is done.
//
// Exactness of the gate: a warp publishes step t only after its CTA passed
// gate t (cnt >= 1024t), so cnt < 1024(t+1) until EVERY warp finished step t.
// WAR safety: slot (t+1)&1 is rewritten only by warps in step t+1, gated on
// cnt >= 1024(t+1), which requires every reader's release-red for step t,
// which orders after that reader's sweep loads of slot t&1... and slot t&1
// is precisely what step-(t+1) writers clobber (as h_{t+2}). All reads done.
// Intra-CTA: bars A/B strictly alternate stage-writes and matvec-reads of
// hs; xs is triple-buffered against the <=1-step warp skew.
// ---------------------------------------------------------------------------
__global__ void __launch_bounds__(256, 1) rec_kernel(
    const float* __restrict__ x,
    const float* __restrict__ Wih,
    const float* __restrict__ Whh,
    const float* __restrict__ bih,
    const float* __restrict__ bhh)
{
    __shared__ __align__(16) float hs[2][H];     // staged h_t
    __shared__ __align__(16) float xs[3][II];    // staged x_t (triple buffer)

    const int tid  = threadIdx.x;
    const int lane = tid & 31;
    const int wrp  = tid >> 5;               // 0..7
    const int u    = blockIdx.x * UPC + wrp; // hidden unit 0..1023

    // ---- W_hh slice into registers (coalesced float2 loads) ----
    unsigned long long wq[4][16];
    #pragma unroll
    for (int g = 0; g < 4; g++) {
        const float2* base = (const float2*)(Whh + (size_t)(g * H + u) * H) + lane;
        #pragma unroll
        for (int k = 0; k < 16; k++) {
            float2 v = base[k * 32];
            wq[g][k] = pk2(v.x, v.y);
        }
    }
    // ---- W_ih slice (cols 2l, 2l+1 of rows u, H+u, 2H+u, 3H+u) ----
    unsigned long long wx[4];
    #pragma unroll
    for (int g = 0; g < 4; g++) {
        float2 v = ((const float2*)(Wih + (size_t)(g * H + u) * II))[lane];
        wx[g] = pk2(v.x, v.y);
    }
    // ---- biases (only lane 0 consumes them) ----
    float bs0 = bih[u]         + bhh[u];
    float bs1 = bih[H + u]     + bhh[H + u];
    float bs2 = bih[2 * H + u] + bhh[2 * H + u];
    float bs3 = bih[3 * H + u] + bhh[3 * H + u];

    // ---- preload x_0 into xs[0] ----
    if (tid < 16) ((float4*)xs[0])[tid] = ((const float4*)x)[tid];
    __syncthreads();

    float c = 0.0f;                          // cell state (lane 0 only)
    const unsigned full = 0xffffffffu;

    #pragma unroll 1
    for (int t = 0; t < S; t++) {
        const int cur = t & 1;

        // 1. prefetch next step's input row (DRAM, hidden behind this step)
        if (t + 1 < S && tid < 16)
            ((float4*)xs[(t + 1) % 3])[tid] =
                __ldcg((const float4*)(x + (size_t)(t + 1) * II) + tid);

        // 2. GATE: single acquire-poller per CTA on the warp-step counter
        if (t > 0 && tid == 0) {
            const unsigned need = (unsigned)t * NW;
            unsigned v;
            do {
                asm volatile("ld.acquire.gpu.global.u32 %0, [%1];"
                             : "=r"(v) : "l"(&g_cnt));
            } while (v < need);
        }
        __syncthreads();                     // bar A

        // 3. SWEEP: single weak 16B load per thread (data stable post-gate)
        ((float4*)hs[cur])[tid] = __ldcg(((const float4*)g_h[cur]) + tid);
        __syncthreads();                     // bar B

        // 4. mat-vec: W_hh * h_t  +  W_ih * x_t  (all packed f32x2)
        unsigned long long a0 = 0ull, a1 = 0ull, a2 = 0ull, a3 = 0ull;
        const unsigned long long* h2p = (const unsigned long long*)hs[cur] + lane;
        #pragma unroll
        for (int k = 0; k < 16; k++) {
            unsigned long long hv = h2p[k * 32];
            FMA2(a0, wq[0][k], hv);
            FMA2(a1, wq[1][k], hv);
            FMA2(a2, wq[2][k], hv);
            FMA2(a3, wq[3][k], hv);
        }
        {
            unsigned long long xv = ((const unsigned long long*)xs[t % 3])[lane];
            FMA2(a0, wx[0], xv);
            FMA2(a1, wx[1], xv);
            FMA2(a2, wx[2], xv);
            FMA2(a3, wx[3], xv);
        }
        float s0, s1, s2, s3, xl, xh;
        upk2(a0, xl, xh); s0 = xl + xh;
        upk2(a1, xl, xh); s1 = xl + xh;
        upk2(a2, xl, xh); s2 = xl + xh;
        upk2(a3, xl, xh); s3 = xl + xh;

        #pragma unroll
        for (int off = 16; off > 0; off >>= 1) {
            s0 += __shfl_xor_sync(full, s0, off);
            s1 += __shfl_xor_sync(full, s1, off);
            s2 += __shfl_xor_sync(full, s2, off);
            s3 += __shfl_xor_sync(full, s3, off);
        }

        // 5. activations + publish + per-warp release signal (lane 0)
        if (lane == 0) {
            const float i_ = sigf(s0 + bs0);
            const float f_ = sigf(s1 + bs1);
            const float g_ = tanhfast(s2 + bs2);
            const float o_ = sigf(s3 + bs3);
            c = fmaf(f_, c, i_ * g_);
            const float hnew = o_ * tanhfast(c);
            __stcg(&g_h[(t + 1) & 1][u], hnew);
            asm volatile("red.release.gpu.global.add.u32 [%0], %1;"
                         :: "l"(&g_cnt), "r"(1u));
        }
        // no trailing bar: bar A of the next iteration re-aligns warps
    }
}

// ---------------------------------------------------------------------------
// Kernel 2: out = h_S @ W_lin^T + b_lin   (O = 1)
// h_S lives in g_h[S & 1] = g_h[0]
// ---------------------------------------------------------------------------
__global__ void __launch_bounds__(1024) out_kernel(
    const float* __restrict__ Wlin,
    const float* __restrict__ blin,
    float* __restrict__ out)
{
    __shared__ float red[32];
    const int tid = threadIdx.x;
    float v = g_h[0][tid] * Wlin[tid];
    #pragma unroll
    for (int off = 16; off > 0; off >>= 1)
        v += __shfl_xor_sync(0xffffffffu, v, off);
    if ((tid & 31) == 0) red[tid >> 5] = v;
    __syncthreads();
    if (tid < 32) {
        float xv = red[tid];
        #pragma unroll
        for (int off = 16; off > 0; off >>= 1)
            xv += __shfl_xor_sync(0xffffffffu, xv, off);
        if (tid == 0) out[0] = xv + blin[0];
    }
}

// ---------------------------------------------------------------------------
// kernel_launch (graph-capturable: plain launches only)
// Input order: input_seq, W_ih, W_hh, b_ih, b_hh, W_lin, b_lin (all fp32)
// 4 nop launches pad the sequence to 7 nodes/replay so ncu (-s 5 -c 1)
// lands on rec_kernel (index 5 mod 7).
// ---------------------------------------------------------------------------
extern "C" void kernel_launch(void* const* d_in, const int* in_sizes, int n_in,
                              void* d_out, int out_size)
{
    const float* x    = (const float*)d_in[0];
    const float* Wih  = (const float*)d_in[1];
    const float* Whh  = (const float*)d_in[2];
    const float* bih  = (const float*)d_in[3];
    const float* bhh  = (const float*)d_in[4];
    const float* Wlin = (const float*)d_in[5];
    const float* blin = (const float*)d_in[6];
    float* out = (float*)d_out;

    reset_kernel<<<1, 1024>>>();
    nop_kernel<<<1, 32>>>();
    nop_kernel<<<1, 32>>>();
    nop_kernel<<<1, 32>>>();
    nop_kernel<<<1, 32>>>();
    rec_kernel<<<NCTA, 256>>>(x, Wih, Whh, bih, bhh);
    out_kernel<<<1, 1024>>>(Wlin, blin, out);
}

// round 10
// speedup vs baseline: 1.2383x; 1.2383x over previous
#include <cuda_runtime.h>
#include <cstdint>

// Problem sizes
#define S    4096
#define II   64
#define H    1024
#define NCTA 128
#define UPC  8        // hidden units per CTA (1 per warp, 8 warps)

// ---------------------------------------------------------------------------
// Device-global scratch (allocation-free rule: __device__ arrays only)
//
// g_h:  double-buffered hidden state (plain f32; h_t lives in slot t&1).
// g_cnt: monotonic CTA-step counter (128 adds per step — NOT 1024: same-
//        address REDs serialize at ~0.854 cy/op in the LTS atomic ALU, so
//        per-warp signaling put ~875 cy/step on the critical path; that was
//        the R9 regression).
//
// Visibility chain (why weak h loads are safe):
//   warp's lane0: weak STG h  ->  atom.add.acq_rel.cta (SMEM turnstile)
//   last warp:    red.release.gpu.add g_cnt
//   consumer:     ld.acquire.gpu g_cnt >= 128*t  ->  __syncthreads  -> weak reads
// acq_rel SMEM atomics chain each warp's prior stores into the last warp's
// gpu-scope release (PTX cumulativity); consumer's acquire completes the
// synchronizes-with edge for the whole CTA.
// ---------------------------------------------------------------------------
__device__ float    g_h[2][H];
__device__ unsigned g_cnt;

// ---------------------------------------------------------------------------
// Helpers
// ---------------------------------------------------------------------------
__device__ __forceinline__ unsigned long long pk2(float x, float y) {
    unsigned long long r;
    asm("mov.b64 %0, {%1,%2};" : "=l"(r) : "f"(x), "f"(y));
    return r;
}
__device__ __forceinline__ void upk2(unsigned long long a, float& x, float& y) {
    asm("mov.b64 {%0,%1}, %2;" : "=f"(x), "=f"(y) : "l"(a));
}
#define FMA2(acc, a, b) \
    asm("fma.rn.f32x2 %0, %1, %2, %0;" : "+l"(acc) : "l"(a), "l"(b))

__device__ __forceinline__ float sigf(float x) {
    return 1.0f / (1.0f + __expf(-x));
}
__device__ __forceinline__ float tanhfast(float x) {
    float ax = fabsf(x);
    float e  = __expf(-2.0f * ax);          // in (0,1], overflow-free
    float t  = __fdividef(1.0f - e, 1.0f + e);
    return copysignf(t, x);
}

// ---------------------------------------------------------------------------
// Kernel 0: reset state between graph replays (determinism requirement)
// ---------------------------------------------------------------------------
__global__ void reset_kernel() {
    int i = threadIdx.x;
    if (i < H) { g_h[0][i] = 0.0f; g_h[1][i] = 0.0f; }
    if (i == 0) g_cnt = 0u;
}

// ---------------------------------------------------------------------------
// Kernel 1: persistent fused LSTM recurrence (input GEMM folded in).
// 128 CTAs x 256 threads, 1 CTA/SM (register bound). Warp w of CTA b owns
// hidden unit u = b*8 + w (gate rows u, H+u, 2H+u, 3H+u).
// Lane l holds W_hh column pairs (2l+64k) k=0..15 (64 packed f32x2) plus
// W_ih column pair 2l (4 packed f32x2) in registers for all 4096 steps.
//
// Per-step protocol (TWO __syncthreads):
//   1. prefetch x_{t+1} (tid<16, 256 B, triple-buffered SMEM)
//   2. GATE: tid 0 spins ld.acquire.gpu on g_cnt until >= 128*t
//   3. bar A
//   4. SWEEP: one WEAK __ldcg float4 per thread -> hs[t&1]
//   5. bar B
//   6. matvec (LDS.64 + FMA2, W_hh + W_ih) -> shfl reduce -> activations
//   7. lane 0: weak __stcg publish of h_{t+1}[u];
//      old = atom.add.acq_rel.cta(smem turnstile, 1);
//      if (old == 8t+7)  red.release.gpu.add(g_cnt, 1)   // last warp out
//      -> signal fires the instant the CTA's last warp finishes; no
//         trailing barrier, no tid-0 wakeup.
//
// Gate exactness: a CTA's red for step t is issued only after all 8 of its
// warps passed the turnstile for step t, so cnt < 128(t+1) until every warp
// chip-wide finished step t.
// WAR safety: slot (t+1)&1 is rewritten only in step t+1, gated on
// cnt >= 128(t+1); each CTA's step-t red is ordered (release) after its
// sweep reads of slot t&1 — the very slot step-(t+1) writers clobber.
// Intra-CTA: bars A/B separate hs stage-writes from matvec reads; a warp
// passes bar A(t+1) only after ALL siblings arrived, i.e. finished step t,
// so xs slot (t+2)%3 never collides with readers of slot t%3.
// ---------------------------------------------------------------------------
__global__ void __launch_bounds__(256, 1) rec_kernel(
    const float* __restrict__ x,
    const float* __restrict__ Wih,
    const float* __restrict__ Whh,
    const float* __restrict__ bih,
    const float* __restrict__ bhh)
{
    __shared__ __align__(16) float hs[2][H];     // staged h_t
    __shared__ __align__(16) float xs[3][II];    // staged x_t (triple buffer)
    __shared__ unsigned turnstile;               // monotonic warp-completion count

    const int tid  = threadIdx.x;
    const int lane = tid & 31;
    const int wrp  = tid >> 5;               // 0..7
    const int u    = blockIdx.x * UPC + wrp; // hidden unit 0..1023

    // ---- W_hh slice into registers (coalesced float2 loads) ----
    unsigned long long wq[4][16];
    #pragma unroll
    for (int g = 0; g < 4; g++) {
        const float2* base = (const float2*)(Whh + (size_t)(g * H + u) * H) + lane;
        #pragma unroll
        for (int k = 0; k < 16; k++) {
            float2 v = base[k * 32];
            wq[g][k] = pk2(v.x, v.y);
        }
    }
    // ---- W_ih slice (cols 2l, 2l+1 of rows u, H+u, 2H+u, 3H+u) ----
    unsigned long long wx[4];
    #pragma unroll
    for (int g = 0; g < 4; g++) {
        float2 v = ((const float2*)(Wih + (size_t)(g * H + u) * II))[lane];
        wx[g] = pk2(v.x, v.y);
    }
    // ---- biases (only lane 0 consumes them) ----
    float bs0 = bih[u]         + bhh[u];
    float bs1 = bih[H + u]     + bhh[H + u];
    float bs2 = bih[2 * H + u] + bhh[2 * H + u];
    float bs3 = bih[3 * H + u] + bhh[3 * H + u];

    // ---- preload x_0, init turnstile ----
    if (tid < 16) ((float4*)xs[0])[tid] = ((const float4*)x)[tid];
    if (tid == 0) turnstile = 0u;
    __syncthreads();

    float c = 0.0f;                          // cell state (lane 0 only)
    const unsigned full = 0xffffffffu;

    #pragma unroll 1
    for (int t = 0; t < S; t++) {
        const int cur = t & 1;

        // 1. prefetch next step's input row (DRAM, hidden behind this step)
        if (t + 1 < S && tid < 16)
            ((float4*)xs[(t + 1) % 3])[tid] =
                __ldcg((const float4*)(x + (size_t)(t + 1) * II) + tid);

        // 2. GATE: single acquire-poller per CTA on the CTA-step counter
        if (t > 0 && tid == 0) {
            const unsigned need = (unsigned)t * NCTA;
            unsigned v;
            do {
                asm volatile("ld.acquire.gpu.global.u32 %0, [%1];"
                             : "=r"(v) : "l"(&g_cnt));
            } while (v < need);
        }
        __syncthreads();                     // bar A

        // 3. SWEEP: single weak 16B load per thread (data stable post-gate)
        ((float4*)hs[cur])[tid] = __ldcg(((const float4*)g_h[cur]) + tid);
        __syncthreads();                     // bar B

        // 4. mat-vec: W_hh * h_t  +  W_ih * x_t  (all packed f32x2)
        unsigned long long a0 = 0ull, a1 = 0ull, a2 = 0ull, a3 = 0ull;
        const unsigned long long* h2p = (const unsigned long long*)hs[cur] + lane;
        #pragma unroll
        for (int k = 0; k < 16; k++) {
            unsigned long long hv = h2p[k * 32];
            FMA2(a0, wq[0][k], hv);
            FMA2(a1, wq[1][k], hv);
            FMA2(a2, wq[2][k], hv);
            FMA2(a3, wq[3][k], hv);
        }
        {
            unsigned long long xv = ((const unsigned long long*)xs[t % 3])[lane];
            FMA2(a0, wx[0], xv);
            FMA2(a1, wx[1], xv);
            FMA2(a2, wx[2], xv);
            FMA2(a3, wx[3], xv);
        }
        float s0, s1, s2, s3, xl, xh;
        upk2(a0, xl, xh); s0 = xl + xh;
        upk2(a1, xl, xh); s1 = xl + xh;
        upk2(a2, xl, xh); s2 = xl + xh;
        upk2(a3, xl, xh); s3 = xl + xh;

        #pragma unroll
        for (int off = 16; off > 0; off >>= 1) {
            s0 += __shfl_xor_sync(full, s0, off);
            s1 += __shfl_xor_sync(full, s1, off);
            s2 += __shfl_xor_sync(full, s2, off);
            s3 += __shfl_xor_sync(full, s3, off);
        }

        // 5. activations + publish + turnstile; last warp out signals chip
        if (lane == 0) {
            const float i_ = sigf(s0 + bs0);
            const float f_ = sigf(s1 + bs1);
            const float g_ = tanhfast(s2 + bs2);
            const float o_ = sigf(s3 + bs3);
            c = fmaf(f_, c, i_ * g_);
            const float hnew = o_ * tanhfast(c);
            __stcg(&g_h[(t + 1) & 1][u], hnew);

            unsigned old;
            asm volatile("atom.acq_rel.cta.add.u32 %0, [%1], %2;"
                         : "=r"(old) : "l"(&turnstile), "r"(1u) : "memory");
            if (old == (unsigned)(t * UPC + (UPC - 1))) {
                asm volatile("red.release.gpu.global.add.u32 [%0], %1;"
                             :: "l"(&g_cnt), "r"(1u));
            }
        }
        // no trailing bar: bar A of the next iteration re-aligns warps
    }
}

// ---------------------------------------------------------------------------
// Kernel 2: out = h_S @ W_lin^T + b_lin   (O = 1)
// h_S lives in g_h[S & 1] = g_h[0]
// ---------------------------------------------------------------------------
__global__ void __launch_bounds__(1024) out_kernel(
    const float* __restrict__ Wlin,
    const float* __restrict__ blin,
    float* __restrict__ out)
{
    __shared__ float red[32];
    const int tid = threadIdx.x;
    float v = g_h[0][tid] * Wlin[tid];
    #pragma unroll
    for (int off = 16; off > 0; off >>= 1)
        v += __shfl_xor_sync(0xffffffffu, v, off);
    if ((tid & 31) == 0) red[tid >> 5] = v;
    __syncthreads();
    if (tid < 32) {
        float xv = red[tid];
        #pragma unroll
        for (int off = 16; off > 0; off >>= 1)
            xv += __shfl_xor_sync(0xffffffffu, xv, off);
        if (tid == 0) out[0] = xv + blin[0];
    }
}

// ---------------------------------------------------------------------------
// kernel_launch (graph-capturable: plain launches only)
// Input order: input_seq, W_ih, W_hh, b_ih, b_hh, W_lin, b_lin (all fp32)
// ---------------------------------------------------------------------------
extern "C" void kernel_launch(void* const* d_in, const int* in_sizes, int n_in,
                              void* d_out, int out_size)
{
    const float* x    = (const float*)d_in[0];
    const float* Wih  = (const float*)d_in[1];
    const float* Whh  = (const float*)d_in[2];
    const float* bih  = (const float*)d_in[3];
    const float* bhh  = (const float*)d_in[4];
    const float* Wlin = (const float*)d_in[5];
    const float* blin = (const float*)d_in[6];
    float* out = (float*)d_out;

    reset_kernel<<<1, 1024>>>();
    rec_kernel<<<NCTA, 256>>>(x, Wih, Whh, bih, bhh);
    out_kernel<<<1, 1024>>>(Wlin, blin, out);
}